// round 2
// baseline (speedup 1.0000x reference)
#include <cuda_runtime.h>
#include <math_constants.h>

#define BATCH 1024
#define NGENE 8192
#define NSETS 2048
#define MAX_TOTAL 262144   // >= 2048 * 120

// Scratch (static device globals — no runtime allocation)
__device__ float g_GT[NGENE * BATCH];   // transposed features, 33.5 MB
__device__ float g_w[MAX_TOTAL];        // softmax weights per edge
__device__ int   g_off[NSETS + 1];      // segment start offsets

// ---------------------------------------------------------------------------
// K1: segment boundary detection (segment_ids sorted, all segments nonempty)
// ---------------------------------------------------------------------------
__global__ void k_offsets(const int* __restrict__ seg, int total) {
    int p = blockIdx.x * blockDim.x + threadIdx.x;
    if (p >= total) return;
    if (p == 0) g_off[0] = 0;
    else {
        int s = seg[p];
        if (seg[p - 1] != s) g_off[s] = p;
    }
    if (p == total - 1) g_off[NSETS] = total;
}

// ---------------------------------------------------------------------------
// K2: warp-per-segment softmax over attn_logits -> g_w
// ---------------------------------------------------------------------------
__global__ void k_softmax(const float* __restrict__ logits) {
    int warp_id = (blockIdx.x * blockDim.x + threadIdx.x) >> 5;
    if (warp_id >= NSETS) return;
    int lane = threadIdx.x & 31;
    int beg = g_off[warp_id];
    int end = g_off[warp_id + 1];

    float m = -CUDART_INF_F;
    for (int p = beg + lane; p < end; p += 32) m = fmaxf(m, logits[p]);
    #pragma unroll
    for (int o = 16; o; o >>= 1) m = fmaxf(m, __shfl_xor_sync(0xFFFFFFFFu, m, o));

    float sum = 0.0f;
    for (int p = beg + lane; p < end; p += 32) {
        float e = __expf(logits[p] - m);
        g_w[p] = e;
        sum += e;
    }
    #pragma unroll
    for (int o = 16; o; o >>= 1) sum += __shfl_xor_sync(0xFFFFFFFFu, sum, o);

    float inv = (sum > 0.0f) ? (1.0f / sum) : 0.0f;
    for (int p = beg + lane; p < end; p += 32) g_w[p] *= inv;
}

// ---------------------------------------------------------------------------
// K3: tiled transpose G(1024 x 8192) -> GT(8192 x 1024)
// blockDim (32,8), grid (NGENE/32, BATCH/32)
// ---------------------------------------------------------------------------
__global__ void k_transpose(const float* __restrict__ G) {
    __shared__ float tile[32][33];
    int gx = blockIdx.x * 32;   // gene base
    int by = blockIdx.y * 32;   // batch base
    int x = gx + threadIdx.x;
    #pragma unroll
    for (int j = 0; j < 32; j += 8)
        tile[threadIdx.y + j][threadIdx.x] = G[(by + threadIdx.y + j) * NGENE + x];
    __syncthreads();
    #pragma unroll
    for (int j = 0; j < 32; j += 8)
        g_GT[(gx + threadIdx.y + j) * BATCH + by + threadIdx.x] =
            tile[threadIdx.x][threadIdx.y + j];
}

// ---------------------------------------------------------------------------
// K4: block-per-segment aggregation.
// 256 threads x float4 -> each thread owns 4 consecutive batch rows.
// Edge list (idx, w) staged in shared; GT rows read as coalesced 4KB bursts.
// ---------------------------------------------------------------------------
__global__ __launch_bounds__(256) void k_agg(const int* __restrict__ flat_idx,
                                             float* __restrict__ out) {
    int s = blockIdx.x;
    int beg = g_off[s];
    int n = g_off[s + 1] - beg;
    if (n > 128) n = 128;   // structural guarantee: n <= 120

    __shared__ int   sh_idx[128];
    __shared__ float sh_w[128];
    int t = threadIdx.x;
    if (t < n) {
        sh_idx[t] = flat_idx[beg + t];
        sh_w[t]   = g_w[beg + t];
    }
    __syncthreads();

    const float4* __restrict__ GT4 = reinterpret_cast<const float4*>(g_GT);
    float4 acc = make_float4(0.f, 0.f, 0.f, 0.f);

    #pragma unroll 4
    for (int i = 0; i < n; i++) {
        float w  = sh_w[i];
        float4 v = GT4[sh_idx[i] * (BATCH / 4) + t];
        acc.x += w * v.x;
        acc.y += w * v.y;
        acc.z += w * v.z;
        acc.w += w * v.w;
    }

    int b = t * 4;
    out[(b + 0) * NSETS + s] = acc.x;
    out[(b + 1) * NSETS + s] = acc.y;
    out[(b + 2) * NSETS + s] = acc.z;
    out[(b + 3) * NSETS + s] = acc.w;
}

// ---------------------------------------------------------------------------
// Launcher (graph-capturable: kernel launches only, default stream ordering)
// Inputs: [0] geneset_features f32 (1024*8192), [1] attn_logits f32 (total),
//         [2] flat_idx i32 (total), [3] segment_ids i32 (total)
// Output: f32 (1024*2048)
// ---------------------------------------------------------------------------
extern "C" void kernel_launch(void* const* d_in, const int* in_sizes, int n_in,
                              void* d_out, int out_size) {
    const float* G      = (const float*)d_in[0];
    const float* logits = (const float*)d_in[1];
    const int*   fidx   = (const int*)d_in[2];
    const int*   seg    = (const int*)d_in[3];
    float*       out    = (float*)d_out;
    int total = in_sizes[1];

    k_offsets<<<(total + 255) / 256, 256>>>(seg, total);
    k_softmax<<<(NSETS * 32 + 255) / 256, 256>>>(logits);
    k_transpose<<<dim3(NGENE / 32, BATCH / 32), dim3(32, 8)>>>(G);
    k_agg<<<NSETS, 256>>>(fidx, out);
}